// round 17
// baseline (speedup 1.0000x reference)
#include <cuda_runtime.h>
#include <cuda_bf16.h>
#include <cuda_fp16.h>
#include <math.h>
#include <stdint.h>

// Problem constants (fixed by the dataset)
#define NMAX 100000
#define EMAX 800000

// Scratch (device globals: allocation-free per harness rules)
__device__ __half g_Wedgeh[(size_t)EMAX * 256];     // 409 MB per-edge 16x16 (fp16)
__device__ float  g_h[3][NMAX * 16];                // slot0 = h0, 1/2 ping-pong
__device__ __half g_W3h0[256 * 64];                 // W3^T fp16 limb hi (n-major)
__device__ __half g_W3h1[256 * 64];                 // W3^T fp16 limb lo
__device__ __half g_W2h0[64 * 64];                  // W2^T fp16 limb hi (n-major)
__device__ __half g_W2h1[64 * 64];                  // W2^T fp16 limb lo

// ---------------------------------------------------------------------------
// mma helper (m16n8k16 fp16, sm_80+, compiles for plain compute_100)
// ---------------------------------------------------------------------------
__device__ __forceinline__ void mma_f16(float* c, const uint32_t* a,
                                        uint32_t b0, uint32_t b1) {
    asm volatile(
        "mma.sync.aligned.m16n8k16.row.col.f32.f16.f16.f32 "
        "{%0,%1,%2,%3}, {%4,%5,%6,%7}, {%8,%9}, {%0,%1,%2,%3};"
        : "+f"(c[0]), "+f"(c[1]), "+f"(c[2]), "+f"(c[3])
        : "r"(a[0]), "r"(a[1]), "r"(a[2]), "r"(a[3]), "r"(b0), "r"(b1));
}

__device__ __forceinline__ uint32_t pack_h2(float v0, float v1) {
    __half2 t = __floats2half2_rn(v0, v1);
    return *reinterpret_cast<uint32_t*>(&t);
}

// W3 [64,256] fp32 -> n-major fp16 limb planes (hi, lo)
__global__ void w3_split_kernel(const float* __restrict__ W3)
{
    int idx = blockIdx.x * blockDim.x + threadIdx.x;
    if (idx >= 64 * 256) return;
    int k = idx >> 8, n = idx & 255;
    float v = W3[idx];
    __half h = __float2half_rn(v);
    g_W3h0[n * 64 + k] = h;
    g_W3h1[n * 64 + k] = __float2half_rn(v - __half2float(h));
}
// W2 [64,64] fp32 -> n-major fp16 limb planes
__global__ void w2_split_kernel(const float* __restrict__ W2)
{
    int idx = blockIdx.x * blockDim.x + threadIdx.x;
    if (idx >= 64 * 64) return;
    int k = idx >> 6, n = idx & 63;
    float v = W2[idx];
    __half h = __float2half_rn(v);
    g_W2h0[n * 64 + k] = h;
    g_W2h1[n * 64 + k] = __float2half_rn(v - __half2float(h));
}

// ---------------------------------------------------------------------------
// FUSED edge pipeline + message-pass-1.
// 512 threads (16 warps, 4/SMSP for latency hiding), warp = 32 edge rows,
// tile = 512 edges. Staging buffer ALIASED onto E1 (rows are warp-private
// and fully consumed before staging begins; __syncwarp ordering only).
//   stage1 (scalar): e1 = relu(ea@W1+b1) -> warp-private smem fp16
//   MMA1 (fp16, 2 products: e1*(W2_hi+W2_lo)): e2 = relu(.@W2+b2)
//   MMA2 (fp16, 2 products: e2*(W3_hi+W3_lo)): Wedge = e2@W3+b3
//   Coalesced Wedge store via staging; msg1 epilogue from register frags.
// Row stride 36 words: fragment banks 4*qr+tg, conflict-free.
// ---------------------------------------------------------------------------
#define FZ_E1     0
#define FZ_W2_0   73728
#define FZ_W2_1   82944
#define FZ_W3_0   92160
#define FZ_W3_1   129024
#define FZ_SMEM   165888

__global__ __launch_bounds__(512, 1)
void fused_edge_kernel(const float* __restrict__ edge_attr,
                       const int* __restrict__ edge_index,
                       const float* __restrict__ W1, const float* __restrict__ b1,
                       const float* __restrict__ b2, const float* __restrict__ b3,
                       int E, int ntiles)
{
    extern __shared__ char smem[];
    uint32_t* E1s  = (uint32_t*)(smem + FZ_E1);     // [512][36] words (fp16x2)
    uint32_t* W2s0 = (uint32_t*)(smem + FZ_W2_0);   // [64][36]  (fp16x2)
    uint32_t* W2s1 = (uint32_t*)(smem + FZ_W2_1);
    uint32_t* W3s0 = (uint32_t*)(smem + FZ_W3_0);   // [256][36] (fp16x2)
    uint32_t* W3s1 = (uint32_t*)(smem + FZ_W3_1);
    uint32_t* STG_S = E1s;                          // alias: staging reuses E1
    __shared__ float W1s[256], b1s[64], b2s[64], b3s[256];

    int tid = threadIdx.x;
    // One-time loads (persistent kernel)
    for (int i = tid; i < 64 * 32; i += 512) {
        int r = i >> 5, w = i & 31;
        W2s0[r * 36 + w] = ((const uint32_t*)g_W2h0)[r * 32 + w];
        W2s1[r * 36 + w] = ((const uint32_t*)g_W2h1)[r * 32 + w];
    }
    for (int i = tid; i < 256 * 32; i += 512) {
        int r = i >> 5, w = i & 31;
        W3s0[r * 36 + w] = ((const uint32_t*)g_W3h0)[r * 32 + w];
        W3s1[r * 36 + w] = ((const uint32_t*)g_W3h1)[r * 32 + w];
    }
    if (tid < 256) { W1s[tid] = W1[tid]; b3s[tid] = b3[tid]; }
    if (tid >= 256 && tid < 320) {
        b1s[tid - 256] = b1[tid - 256];
        b2s[tid - 256] = b2[tid - 256];
    }
    __syncthreads();

    int lane = tid & 31, wid = tid >> 5;
    int qr = lane >> 2, tg = lane & 3;
    int mrow = wid * 32;                    // warp's 32-row block (16 warps)
    const float4* W1s4 = (const float4*)W1s;
    const float4* b1s4 = (const float4*)b1s;
    const float*  h0g  = g_h[0];
    float*        h1g  = g_h[1];

    for (int t = blockIdx.x; t < ntiles; t += gridDim.x) {
        size_t ebase = (size_t)t * 512;

        // ---- stage 1: thread tid -> edge row tid; warp-private rows ----
        {
            size_t e = ebase + (size_t)tid;
            float4 a = make_float4(0.f, 0.f, 0.f, 0.f);
            float vm = 0.f;
            if (e < (size_t)E) { a = ((const float4*)edge_attr)[e]; vm = 1.f; }
#pragma unroll
            for (int m4 = 0; m4 < 16; ++m4) {
                float4 w0 = W1s4[m4];
                float4 w1 = W1s4[16 + m4];
                float4 w2 = W1s4[32 + m4];
                float4 w3 = W1s4[48 + m4];
                float4 bb = b1s4[m4];
                float v0 = vm * fmaxf(bb.x + a.x*w0.x + a.y*w1.x + a.z*w2.x + a.w*w3.x, 0.f);
                float v1 = vm * fmaxf(bb.y + a.x*w0.y + a.y*w1.y + a.z*w2.y + a.w*w3.y, 0.f);
                float v2 = vm * fmaxf(bb.z + a.x*w0.z + a.y*w1.z + a.z*w2.z + a.w*w3.z, 0.f);
                float v3 = vm * fmaxf(bb.w + a.x*w0.w + a.y*w1.w + a.z*w2.w + a.w*w3.w, 0.f);
                E1s[tid * 36 + 2 * m4]     = pack_h2(v0, v1);
                E1s[tid * 36 + 2 * m4 + 1] = pack_h2(v2, v3);
            }
        }
        __syncwarp();

        // ---- per-lane edge metadata for the 4 fragment rows ----
        int srcs[4], dsts[4];
        bool rv[4];
        float pacc[4][4];
#pragma unroll
        for (int rr = 0; rr < 4; ++rr) {
            int row = mrow + (rr >> 1) * 16 + (rr & 1) * 8 + qr;
            size_t e = ebase + (size_t)row;
            rv[rr] = e < (size_t)E;
            srcs[rr] = rv[rr] ? edge_index[2 * e]     : 0;
            dsts[rr] = rv[rr] ? edge_index[2 * e + 1] : 0;
            pacc[rr][0] = 0.f; pacc[rr][1] = 0.f;
            pacc[rr][2] = 0.f; pacc[rr][3] = 0.f;
        }

        // ---- MMA1: e2 = relu(e1 @ W2 + b2), fp16 2-product ----
        float cc1[2][8][4];
#pragma unroll
        for (int mt = 0; mt < 2; ++mt)
#pragma unroll
            for (int nt = 0; nt < 8; ++nt) {
                cc1[mt][nt][0] = 0.f; cc1[mt][nt][1] = 0.f;
                cc1[mt][nt][2] = 0.f; cc1[mt][nt][3] = 0.f;
            }
#pragma unroll
        for (int ks = 0; ks < 4; ++ks) {
            int kofs = ks * 8 + tg;
            uint32_t a0[2][4];
#pragma unroll
            for (int mt = 0; mt < 2; ++mt) {
                int r0 = mrow + mt * 16 + qr;
                a0[mt][0] = E1s[r0 * 36 + kofs];
                a0[mt][1] = E1s[(r0 + 8) * 36 + kofs];
                a0[mt][2] = E1s[r0 * 36 + kofs + 4];
                a0[mt][3] = E1s[(r0 + 8) * 36 + kofs + 4];
            }
#pragma unroll
            for (int nt = 0; nt < 8; ++nt) {
                int n = nt * 8 + qr;
                uint32_t b00 = W2s0[n * 36 + kofs];
                uint32_t b01 = W2s0[n * 36 + kofs + 4];
                uint32_t b10 = W2s1[n * 36 + kofs];
                uint32_t b11 = W2s1[n * 36 + kofs + 4];
#pragma unroll
                for (int mt = 0; mt < 2; ++mt) {
                    mma_f16(cc1[mt][nt], a0[mt], b00, b01);
                    mma_f16(cc1[mt][nt], a0[mt], b10, b11);
                }
            }
        }

        // ---- relu(+b2) and repack C1 fragments as fp16 A2 fragments ----
        uint32_t a2h[2][4][4];
#pragma unroll
        for (int mt = 0; mt < 2; ++mt)
#pragma unroll
            for (int nt = 0; nt < 8; ++nt) {
                float bb0 = b2s[nt * 8 + 2 * tg];
                float bb1 = b2s[nt * 8 + 2 * tg + 1];
                float d0 = fmaxf(cc1[mt][nt][0] + bb0, 0.f);
                float d1 = fmaxf(cc1[mt][nt][1] + bb1, 0.f);
                float d2 = fmaxf(cc1[mt][nt][2] + bb0, 0.f);
                float d3 = fmaxf(cc1[mt][nt][3] + bb1, 0.f);
                int ks2 = nt >> 1, q = (nt & 1) * 2;
                a2h[mt][ks2][q]     = pack_h2(d0, d1);
                a2h[mt][ks2][q + 1] = pack_h2(d2, d3);
            }
        __syncwarp();   // all MMA1 reads of this warp's E1 rows done -> staging OK

        // ---- MMA2 (fp16) + staged coalesced store + msg1 epilogue ----
        uint4* outw4 = (uint4*)g_Wedgeh;
#pragma unroll
        for (int grp = 0; grp < 4; ++grp) {
            int noff = grp * 64;
            float cc2[2][8][4];
#pragma unroll
            for (int mt = 0; mt < 2; ++mt)
#pragma unroll
                for (int nt = 0; nt < 8; ++nt) {
                    cc2[mt][nt][0] = 0.f; cc2[mt][nt][1] = 0.f;
                    cc2[mt][nt][2] = 0.f; cc2[mt][nt][3] = 0.f;
                }
#pragma unroll
            for (int ks = 0; ks < 4; ++ks) {
                int kofs = ks * 8 + tg;
#pragma unroll
                for (int nt = 0; nt < 8; ++nt) {
                    int n = noff + nt * 8 + qr;
                    uint32_t b00 = W3s0[n * 36 + kofs];
                    uint32_t b01 = W3s0[n * 36 + kofs + 4];
                    uint32_t b10 = W3s1[n * 36 + kofs];
                    uint32_t b11 = W3s1[n * 36 + kofs + 4];
#pragma unroll
                    for (int mt = 0; mt < 2; ++mt) {
                        mma_f16(cc2[mt][nt], a2h[mt][ks], b00, b01);
                        mma_f16(cc2[mt][nt], a2h[mt][ks], b10, b11);
                    }
                }
            }

            // h0[src] float4 for this grp (i = 4*grp + nt>>1), per fragment row
            float4 hv[4];
#pragma unroll
            for (int rr = 0; rr < 4; ++rr)
                hv[rr] = rv[rr]
                    ? ((const float4*)(h0g + (size_t)srcs[rr] * 16))[grp]
                    : make_float4(0.f, 0.f, 0.f, 0.f);

            // Stage fp16 (+b3) into smem (conflict-free) + accumulate msg1
#pragma unroll
            for (int mt = 0; mt < 2; ++mt) {
                int row0 = mrow + mt * 16 + qr;
                int rr0 = mt * 2, rr1 = mt * 2 + 1;
#pragma unroll
                for (int nt = 0; nt < 8; ++nt) {
                    int n0 = noff + nt * 8 + 2 * tg;
                    float bb0 = b3s[n0], bb1 = b3s[n0 + 1];
                    float w0 = cc2[mt][nt][0] + bb0;
                    float w1 = cc2[mt][nt][1] + bb1;
                    float w2v = cc2[mt][nt][2] + bb0;
                    float w3v = cc2[mt][nt][3] + bb1;
                    int s = (nt & 1) * 2;
                    float hc0 = ((const float*)&hv[rr0])[nt >> 1];
                    float hc1 = ((const float*)&hv[rr1])[nt >> 1];
                    pacc[rr0][s]     += hc0 * w0;
                    pacc[rr0][s + 1] += hc0 * w1;
                    pacc[rr1][s]     += hc1 * w2v;
                    pacc[rr1][s + 1] += hc1 * w3v;
                    // banks = (4*row + 4*nt + tg) mod 32 -> 32 distinct
                    STG_S[row0 * 36 + nt * 4 + tg]       = pack_h2(w0, w1);
                    STG_S[(row0 + 8) * 36 + nt * 4 + tg] = pack_h2(w2v, w3v);
                }
            }
            __syncwarp();

            // Coalesced flush: per instr 4 rows x 8 lanes = 4x128B contiguous
#pragma unroll
            for (int it = 0; it < 8; ++it) {
                int row = mrow + it * 4 + (lane >> 3);
                int w4  = lane & 7;
                size_t e = ebase + (size_t)row;
                if (e < (size_t)E) {
                    const uint32_t* sp = STG_S + row * 36 + w4 * 4;
                    uint4 v = make_uint4(sp[0], sp[1], sp[2], sp[3]);
                    outw4[e * 32 + grp * 8 + w4] = v;
                }
            }
            __syncwarp();   // staging reusable for next grp / next tile
        }

        // ---- flush msg1 partials: o = (s>>1)*8 + (s&1) + 2*tg ----
#pragma unroll
        for (int rr = 0; rr < 4; ++rr) {
            if (!rv[rr]) continue;
            float* dh = h1g + (size_t)dsts[rr] * 16;
            atomicAdd(dh + 2 * tg,     pacc[rr][0]);
            atomicAdd(dh + 2 * tg + 1, pacc[rr][1]);
            atomicAdd(dh + 2 * tg + 8, pacc[rr][2]);
            atomicAdd(dh + 2 * tg + 9, pacc[rr][3]);
        }
    }
}

// ---------------------------------------------------------------------------
// h0 = [x | zeros]
// ---------------------------------------------------------------------------
__global__ void init_h_kernel(const float* __restrict__ x, int N)
{
    int idx = blockIdx.x * blockDim.x + threadIdx.x;
    if (idx >= N * 16) return;
    int n = idx >> 4, i = idx & 15;
    g_h[0][idx] = (i < 8) ? x[n * 8 + i] : 0.f;
}

// h_out = bias + h_in @ root
__global__ void node_init_kernel(int in_slot, int out_slot,
                                 const float* __restrict__ root,
                                 const float* __restrict__ bias, int N)
{
    __shared__ float rs[256];
    __shared__ float bs[16];
    int tid = threadIdx.x;
    if (tid < 256) rs[tid] = root[tid];
    if (tid < 16)  bs[tid] = bias[tid];
    __syncthreads();
    int idx = blockIdx.x * blockDim.x + tid;
    if (idx >= N * 16) return;
    int n = idx >> 4, o = idx & 15;
    const float* hr = g_h[in_slot] + n * 16;
    float acc = bs[o];
#pragma unroll
    for (int i = 0; i < 16; ++i) acc += hr[i] * rs[i * 16 + o];
    g_h[out_slot][idx] = acc;
}

// Message pass: h_out[dst] += h_in[src] @ Wedge[e] (fp16). One warp per edge.
__global__ __launch_bounds__(256)
void msg_kernel(int in_slot, int out_slot, const int* __restrict__ edge_index, int E)
{
    int lane = threadIdx.x & 31;
    int e = (blockIdx.x * 256 + threadIdx.x) >> 5;
    if (e >= E) return;
    int src = edge_index[2 * e];
    int dst = edge_index[2 * e + 1];

    const float* h_in = g_h[in_slot] + (size_t)src * 16;
    float hv = (lane < 16) ? h_in[lane] : 0.f;

    const uint32_t* W = (const uint32_t*)(g_Wedgeh + (size_t)e * 256);
    float p0 = 0.f, p1 = 0.f;
    int ib = lane >> 3;
#pragma unroll
    for (int j = 0; j < 4; ++j) {
        uint32_t wv = W[lane + 32 * j];
        __half2 h2 = *reinterpret_cast<__half2*>(&wv);
        float2 wf = __half22float2(h2);
        float hk = __shfl_sync(0xffffffffu, hv, ib + 4 * j);
        p0 += hk * wf.x;
        p1 += hk * wf.y;
    }
    p0 += __shfl_xor_sync(0xffffffffu, p0, 8);
    p1 += __shfl_xor_sync(0xffffffffu, p1, 8);
    p0 += __shfl_xor_sync(0xffffffffu, p0, 16);
    p1 += __shfl_xor_sync(0xffffffffu, p1, 16);
    if (lane < 8) {
        float* dsth = &g_h[out_slot][(size_t)dst * 16 + 2 * lane];
        atomicAdd(dsth, p0);
        atomicAdd(dsth + 1, p1);
    }
}

// ---------------------------------------------------------------------------
// Readout
// ---------------------------------------------------------------------------
__global__ void zero_out_kernel(float* out)
{
    if (threadIdx.x == 0 && blockIdx.x == 0) out[0] = 0.f;
}

__global__ __launch_bounds__(256)
void readout_kernel(int h_slot,
                    const float* __restrict__ Wi1, const float* __restrict__ bi1,
                    const float* __restrict__ Wi2, const float* __restrict__ bi2,
                    const float* __restrict__ Wj1, const float* __restrict__ bj1,
                    const float* __restrict__ Wj2, const float* __restrict__ bj2,
                    float* __restrict__ out, int N)
{
    __shared__ float Wi1s[4096], Wj1s[2048];
    __shared__ float bi1s[128], bj1s[128], Wi2s[128], Wj2s[128];
    __shared__ float warpsum[8];

    int tid = threadIdx.x;
    for (int i = tid; i < 4096; i += 256) Wi1s[i] = Wi1[i];
    for (int i = tid; i < 2048; i += 256) Wj1s[i] = Wj1[i];
    if (tid < 128) {
        bi1s[tid] = bi1[tid]; bj1s[tid] = bj1[tid];
        Wi2s[tid] = Wi2[tid]; Wj2s[tid] = Wj2[tid];
    }
    __syncthreads();

    int lane = tid & 31, w = tid >> 5;
    int n = blockIdx.x * 8 + w;
    float contrib = 0.f;

    if (n < N) {
        const float* h  = g_h[h_slot] + n * 16;
        const float* h0 = g_h[0] + n * 16;
        float hv  = (lane < 16) ? h[lane]  : 0.f;
        float h0v = (lane < 16) ? h0[lane] : 0.f;

        float a0 = bi1s[lane], a1 = bi1s[lane + 32], a2 = bi1s[lane + 64], a3 = bi1s[lane + 96];
#pragma unroll
        for (int c = 0; c < 32; ++c) {
            float cc = __shfl_sync(0xffffffffu, (c < 16) ? hv : h0v, c & 15);
            a0 += cc * Wi1s[c * 128 + lane];
            a1 += cc * Wi1s[c * 128 + lane + 32];
            a2 += cc * Wi1s[c * 128 + lane + 64];
            a3 += cc * Wi1s[c * 128 + lane + 96];
        }
        a0 = fmaxf(a0, 0.f); a1 = fmaxf(a1, 0.f); a2 = fmaxf(a2, 0.f); a3 = fmaxf(a3, 0.f);
        float g = a0 * Wi2s[lane] + a1 * Wi2s[lane + 32] + a2 * Wi2s[lane + 64] + a3 * Wi2s[lane + 96];

        float v0 = bj1s[lane], v1 = bj1s[lane + 32], v2 = bj1s[lane + 64], v3 = bj1s[lane + 96];
#pragma unroll
        for (int c = 0; c < 16; ++c) {
            float cc = __shfl_sync(0xffffffffu, hv, c);
            v0 += cc * Wj1s[c * 128 + lane];
            v1 += cc * Wj1s[c * 128 + lane + 32];
            v2 += cc * Wj1s[c * 128 + lane + 64];
            v3 += cc * Wj1s[c * 128 + lane + 96];
        }
        v0 = fmaxf(v0, 0.f); v1 = fmaxf(v1, 0.f); v2 = fmaxf(v2, 0.f); v3 = fmaxf(v3, 0.f);
        float vv = v0 * Wj2s[lane] + v1 * Wj2s[lane + 32] + v2 * Wj2s[lane + 64] + v3 * Wj2s[lane + 96];

#pragma unroll
        for (int s = 16; s > 0; s >>= 1) {
            g  += __shfl_xor_sync(0xffffffffu, g, s);
            vv += __shfl_xor_sync(0xffffffffu, vv, s);
        }
        if (lane == 0) {
            float gate = 1.f / (1.f + expf(-(g + bi2[0])));
            contrib = gate * (vv + bj2[0]);
        }
    }
    if (lane == 0) warpsum[w] = contrib;
    __syncthreads();
    if (tid == 0) {
        float s = 0.f;
#pragma unroll
        for (int i = 0; i < 8; ++i) s += warpsum[i];
        atomicAdd(out, s);
    }
}

// ===========================================================================
extern "C" void kernel_launch(void* const* d_in, const int* in_sizes, int n_in,
                              void* d_out, int out_size)
{
    const float* x          = (const float*)d_in[0];
    const int*   edge_index = (const int*)  d_in[1];
    const float* edge_attr  = (const float*)d_in[2];
    const float* W1  = (const float*)d_in[3];
    const float* b1  = (const float*)d_in[4];
    const float* W2  = (const float*)d_in[5];
    const float* b2  = (const float*)d_in[6];
    const float* W3  = (const float*)d_in[7];
    const float* b3  = (const float*)d_in[8];
    const float* root = (const float*)d_in[9];
    const float* bias = (const float*)d_in[10];
    const float* Wi1 = (const float*)d_in[11];
    const float* bi1 = (const float*)d_in[12];
    const float* Wi2 = (const float*)d_in[13];
    const float* bi2 = (const float*)d_in[14];
    const float* Wj1 = (const float*)d_in[15];
    const float* bj1 = (const float*)d_in[16];
    const float* Wj2 = (const float*)d_in[17];
    const float* bj2 = (const float*)d_in[18];

    int N = in_sizes[0] / 8;  if (N > NMAX) N = NMAX;
    int E = in_sizes[1] / 2;  if (E > EMAX) E = EMAX;
    float* out = (float*)d_out;

    cudaFuncSetAttribute(fused_edge_kernel,
                         cudaFuncAttributeMaxDynamicSharedMemorySize, FZ_SMEM);

    int node_blocks = (N * 16 + 255) / 256;
    int edge_blocks = (E + 7) / 8;
    int ntiles      = (E + 511) / 512;
    int fused_grid  = ntiles < 148 ? ntiles : 148;

    w3_split_kernel<<<64, 256>>>(W3);
    w2_split_kernel<<<16, 256>>>(W2);
    init_h_kernel<<<node_blocks, 256>>>(x, N);
    node_init_kernel<<<node_blocks, 256>>>(0, 1, root, bias, N);
    zero_out_kernel<<<1, 32>>>(out);

    // Fused: edge MLP + coalesced Wedge store + message pass 1 (0 -> 1)
    fused_edge_kernel<<<fused_grid, 512, FZ_SMEM>>>(edge_attr, edge_index,
                                                    W1, b1, b2, b3, E, ntiles);

    // Passes 2 and 3
    node_init_kernel<<<node_blocks, 256>>>(1, 2, root, bias, N);
    msg_kernel<<<edge_blocks, 256>>>(1, 2, edge_index, E);
    node_init_kernel<<<node_blocks, 256>>>(2, 1, root, bias, N);
    msg_kernel<<<edge_blocks, 256>>>(2, 1, edge_index, E);

    readout_kernel<<<(N + 7) / 8, 256>>>(1, Wi1, bi1, Wi2, bi2,
                                         Wj1, bj1, Wj2, bj2, out, N);
}